// round 1
// baseline (speedup 1.0000x reference)
#include <cuda_runtime.h>

#define NN 50000
#define EE 400000
#define DD 128
#define HH 2
#define CC 128
#define TE (EE + NN)

// ---------------- static scratch (no allocations allowed) ----------------
__device__ float  g_xn[NN * DD];          // relu(layernorm(x))
__device__ float  g_h[NN * HH * CC];      // projected features [N, 256]
__device__ float2 g_asrc[NN];             // alpha_src per head
__device__ float2 g_adst[NN];             // alpha_dst per head
__device__ int    g_rowptr[NN + 1];
__device__ int    g_wptr[NN];
__device__ int    g_col[TE];
__device__ int    g_cnt[NN];
__device__ int    g_bsum[64];

// ---------------- packed f32x2 FMA (Blackwell dual-issue fp32) ----------------
__device__ __forceinline__ float2 fma2(float2 a, float2 b, float2 c) {
    unsigned long long ua = *reinterpret_cast<unsigned long long*>(&a);
    unsigned long long ub = *reinterpret_cast<unsigned long long*>(&b);
    unsigned long long uc = *reinterpret_cast<unsigned long long*>(&c);
    unsigned long long ud;
    asm("fma.rn.f32x2 %0, %1, %2, %3;" : "=l"(ud) : "l"(ua), "l"(ub), "l"(uc));
    return *reinterpret_cast<float2*>(&ud);
}

// ---------------- CSR build ----------------
__global__ void k_init(int n) {
    int i = blockIdx.x * blockDim.x + threadIdx.x;
    if (i < n) g_cnt[i] = 1;  // self-loop
}

__global__ void k_count(const int* __restrict__ ei, int E) {
    int e = blockIdx.x * blockDim.x + threadIdx.x;
    if (e < E) atomicAdd(&g_cnt[ei[E + e]], 1);
}

__global__ void k_scan1(int n) {
    __shared__ int wsum[32];
    int i = blockIdx.x * 1024 + threadIdx.x;
    int v = (i < n) ? g_cnt[i] : 0;
    int lane = threadIdx.x & 31, w = threadIdx.x >> 5;
    int s = v;
#pragma unroll
    for (int o = 1; o < 32; o <<= 1) {
        int t = __shfl_up_sync(0xffffffffu, s, o);
        if (lane >= o) s += t;
    }
    if (lane == 31) wsum[w] = s;
    __syncthreads();
    if (w == 0) {
        int t = wsum[lane];
#pragma unroll
        for (int o = 1; o < 32; o <<= 1) {
            int u = __shfl_up_sync(0xffffffffu, t, o);
            if (lane >= o) t += u;
        }
        wsum[lane] = t;
    }
    __syncthreads();
    int off  = (w > 0) ? wsum[w - 1] : 0;
    int incl = s + off;
    if (i < n) g_rowptr[i] = incl - v;  // exclusive
    if (threadIdx.x == 1023) g_bsum[blockIdx.x] = incl;
}

__global__ void k_scan2(int nb) {
    if (threadIdx.x == 0) {
        int acc = 0;
        for (int i = 0; i < nb; i++) { int t = g_bsum[i]; g_bsum[i] = acc; acc += t; }
    }
}

__global__ void k_scan3(int n, int tot) {
    int i = blockIdx.x * blockDim.x + threadIdx.x;
    if (i < n) {
        int r = g_rowptr[i] + g_bsum[i >> 10];
        g_rowptr[i] = r;
        g_wptr[i]   = r;
    }
    if (i == 0) g_rowptr[n] = tot;
}

__global__ void k_scatter(const int* __restrict__ ei, int E, int n) {
    int e = blockIdx.x * blockDim.x + threadIdx.x;
    int tot = E + n;
    if (e >= tot) return;
    int s, d;
    if (e < E) { s = ei[e]; d = ei[E + e]; }
    else       { s = e - E; d = s; }
    int p = atomicAdd(&g_wptr[d], 1);
    g_col[p] = s;
}

// ---------------- LayerNorm + ReLU (warp per row) ----------------
__global__ void k_ln(const float* __restrict__ x, const float* __restrict__ gamma,
                     const float* __restrict__ beta, int n) {
    int row = blockIdx.x * 8 + (threadIdx.x >> 5);
    if (row >= n) return;
    int lane = threadIdx.x & 31;
    float4 v = *reinterpret_cast<const float4*>(&x[row * DD + lane * 4]);
    float s = v.x + v.y + v.z + v.w;
    float q = v.x * v.x + v.y * v.y + v.z * v.z + v.w * v.w;
#pragma unroll
    for (int o = 16; o > 0; o >>= 1) {
        s += __shfl_xor_sync(0xffffffffu, s, o);
        q += __shfl_xor_sync(0xffffffffu, q, o);
    }
    float mu  = s * (1.0f / DD);
    float var = q * (1.0f / DD) - mu * mu;
    float rs  = rsqrtf(var + 1e-5f);
    float4 g = *reinterpret_cast<const float4*>(&gamma[lane * 4]);
    float4 b = *reinterpret_cast<const float4*>(&beta[lane * 4]);
    float4 o4;
    o4.x = fmaxf(0.f, (v.x - mu) * rs * g.x + b.x);
    o4.y = fmaxf(0.f, (v.y - mu) * rs * g.y + b.y);
    o4.z = fmaxf(0.f, (v.z - mu) * rs * g.z + b.z);
    o4.w = fmaxf(0.f, (v.w - mu) * rs * g.w + b.w);
    *reinterpret_cast<float4*>(&g_xn[row * DD + lane * 4]) = o4;
}

// ---------------- GEMM: g_h = g_xn @ W   (M x 128) @ (128 x 256) ----------------
// Block tile 128x128, 256 threads, 8x8 per thread (rows packed in f32x2 pairs).
// A staged k-major so row pairs load as float2; B staged value-duplicated so
// the f32x2 FMA needs zero pack instructions.
__global__ __launch_bounds__(256, 2) void k_gemm(const float* __restrict__ B, int M) {
    __shared__ __align__(16) float  As[16][128];   // [k][row]
    __shared__ __align__(16) float2 Bs[16][128];   // [k][col] duplicated

    int tid = threadIdx.x;
    int tx  = tid & 15;   // col lane
    int ty  = tid >> 4;   // row group
    int row0 = blockIdx.x * 128;
    int col0 = blockIdx.y * 128;

    float2 acc[4][8];
#pragma unroll
    for (int p = 0; p < 4; p++)
#pragma unroll
        for (int j = 0; j < 8; j++) acc[p][j] = make_float2(0.f, 0.f);

    for (int k0 = 0; k0 < 128; k0 += 16) {
        // stage A chunk: 128 rows x 16 k
#pragma unroll
        for (int jj = 0; jj < 2; jj++) {
            int i = tid * 2 + jj;            // 0..511
            int r = i >> 2, q = i & 3;
            int gr = row0 + r;
            if (gr >= M) gr = M - 1;
            float4 v = *reinterpret_cast<const float4*>(&g_xn[gr * DD + k0 + q * 4]);
            As[q * 4 + 0][r] = v.x;
            As[q * 4 + 1][r] = v.y;
            As[q * 4 + 2][r] = v.z;
            As[q * 4 + 3][r] = v.w;
        }
        // stage B chunk: 16 k x 128 cols, duplicated
#pragma unroll
        for (int jj = 0; jj < 2; jj++) {
            int i = tid * 2 + jj;
            int kk = i >> 5, q = i & 31;
            float4 v = *reinterpret_cast<const float4*>(&B[(k0 + kk) * 256 + col0 + q * 4]);
            float4 lo = make_float4(v.x, v.x, v.y, v.y);
            float4 hi = make_float4(v.z, v.z, v.w, v.w);
            *reinterpret_cast<float4*>(&Bs[kk][q * 4 + 0]) = lo;
            *reinterpret_cast<float4*>(&Bs[kk][q * 4 + 2]) = hi;
        }
        __syncthreads();
#pragma unroll
        for (int k = 0; k < 16; k++) {
            float2 a[4];
#pragma unroll
            for (int p = 0; p < 4; p++)
                a[p] = *reinterpret_cast<const float2*>(&As[k][ty * 8 + 2 * p]);
            float2 b[8];
#pragma unroll
            for (int j = 0; j < 8; j++) b[j] = Bs[k][tx + 16 * j];
#pragma unroll
            for (int p = 0; p < 4; p++)
#pragma unroll
                for (int j = 0; j < 8; j++) acc[p][j] = fma2(a[p], b[j], acc[p][j]);
        }
        __syncthreads();
    }
#pragma unroll
    for (int p = 0; p < 4; p++) {
        int r = row0 + ty * 8 + 2 * p;
#pragma unroll
        for (int j = 0; j < 8; j++) {
            int c = col0 + tx + 16 * j;
            if (r < M)     g_h[r * 256 + c]       = acc[p][j].x;
            if (r + 1 < M) g_h[(r + 1) * 256 + c] = acc[p][j].y;
        }
    }
}

// ---------------- attention coefficients (warp per row) ----------------
__global__ void k_alpha(const float* __restrict__ as_, const float* __restrict__ ad_, int n) {
    int row = blockIdx.x * 8 + (threadIdx.x >> 5);
    if (row >= n) return;
    int lane = threadIdx.x & 31;
    float4 h0 = *reinterpret_cast<const float4*>(&g_h[row * 256 + lane * 4]);
    float4 h1 = *reinterpret_cast<const float4*>(&g_h[row * 256 + 128 + lane * 4]);
    float4 a0 = *reinterpret_cast<const float4*>(&as_[lane * 4]);
    float4 a1 = *reinterpret_cast<const float4*>(&as_[128 + lane * 4]);
    float4 d0 = *reinterpret_cast<const float4*>(&ad_[lane * 4]);
    float4 d1 = *reinterpret_cast<const float4*>(&ad_[128 + lane * 4]);
    float s0 = h0.x * a0.x + h0.y * a0.y + h0.z * a0.z + h0.w * a0.w;
    float s1 = h1.x * a1.x + h1.y * a1.y + h1.z * a1.z + h1.w * a1.w;
    float t0 = h0.x * d0.x + h0.y * d0.y + h0.z * d0.z + h0.w * d0.w;
    float t1 = h1.x * d1.x + h1.y * d1.y + h1.z * d1.z + h1.w * d1.w;
#pragma unroll
    for (int o = 16; o > 0; o >>= 1) {
        s0 += __shfl_xor_sync(0xffffffffu, s0, o);
        s1 += __shfl_xor_sync(0xffffffffu, s1, o);
        t0 += __shfl_xor_sync(0xffffffffu, t0, o);
        t1 += __shfl_xor_sync(0xffffffffu, t1, o);
    }
    if (lane == 0) {
        g_asrc[row] = make_float2(s0, s1);
        g_adst[row] = make_float2(t0, t1);
    }
}

// ---------------- fused segment softmax + aggregation (warp per dst node) -------
__global__ void k_agg(const float* __restrict__ bias, const float* __restrict__ resid,
                      float* __restrict__ out, int n) {
    int node = blockIdx.x * 8 + (threadIdx.x >> 5);
    if (node >= n) return;
    int lane = threadIdx.x & 31;
    int s = g_rowptr[node], t = g_rowptr[node + 1];
    float2 ad = g_adst[node];

    float m0 = -1e30f, m1 = -1e30f;
    for (int e = s + lane; e < t; e += 32) {
        float2 as = g_asrc[g_col[e]];
        float e0 = as.x + ad.x; e0 = e0 > 0.f ? e0 : 0.2f * e0;
        float e1 = as.y + ad.y; e1 = e1 > 0.f ? e1 : 0.2f * e1;
        m0 = fmaxf(m0, e0); m1 = fmaxf(m1, e1);
    }
#pragma unroll
    for (int o = 16; o > 0; o >>= 1) {
        m0 = fmaxf(m0, __shfl_xor_sync(0xffffffffu, m0, o));
        m1 = fmaxf(m1, __shfl_xor_sync(0xffffffffu, m1, o));
    }

    float4 a0 = make_float4(0.f, 0.f, 0.f, 0.f), a1 = a0;
    float s0 = 0.f, s1 = 0.f;
    for (int e = s; e < t; e++) {
        int c = g_col[e];                       // warp-uniform -> broadcast load
        float2 as = g_asrc[c];
        float e0 = as.x + ad.x; e0 = e0 > 0.f ? e0 : 0.2f * e0;
        float e1 = as.y + ad.y; e1 = e1 > 0.f ? e1 : 0.2f * e1;
        float w0 = __expf(e0 - m0), w1 = __expf(e1 - m1);
        s0 += w0; s1 += w1;
        float4 h0 = *reinterpret_cast<const float4*>(&g_h[c * 256 + lane * 4]);
        float4 h1 = *reinterpret_cast<const float4*>(&g_h[c * 256 + 128 + lane * 4]);
        a0.x += h0.x * w0; a0.y += h0.y * w0; a0.z += h0.z * w0; a0.w += h0.w * w0;
        a1.x += h1.x * w1; a1.y += h1.y * w1; a1.z += h1.z * w1; a1.w += h1.w * w1;
    }
    float i0 = 0.5f / (s0 + 1e-16f);
    float i1 = 0.5f / (s1 + 1e-16f);
    float4 bb = *reinterpret_cast<const float4*>(&bias[lane * 4]);
    float4 rr = *reinterpret_cast<const float4*>(&resid[node * DD + lane * 4]);
    float4 o4;
    o4.x = a0.x * i0 + a1.x * i1 + bb.x + rr.x;
    o4.y = a0.y * i0 + a1.y * i1 + bb.y + rr.y;
    o4.z = a0.z * i0 + a1.z * i1 + bb.z + rr.z;
    o4.w = a0.w * i0 + a1.w * i1 + bb.w + rr.w;
    *reinterpret_cast<float4*>(&out[node * DD + lane * 4]) = o4;
}

// ---------------- launch ----------------
extern "C" void kernel_launch(void* const* d_in, const int* in_sizes, int n_in,
                              void* d_out, int out_size) {
    const float* x       = (const float*)d_in[0];
    const int*   ei      = (const int*)d_in[1];
    const float* W       = (const float*)d_in[2];
    const float* att_src = (const float*)d_in[3];
    const float* att_dst = (const float*)d_in[4];
    const float* bias    = (const float*)d_in[5];
    const float* gamma   = (const float*)d_in[6];
    const float* beta    = (const float*)d_in[7];
    float* out = (float*)d_out;

    int Nn  = in_sizes[0] / DD;
    int E   = in_sizes[1] / 2;
    int tot = E + Nn;

    k_init<<<(Nn + 255) / 256, 256>>>(Nn);
    k_count<<<(E + 255) / 256, 256>>>(ei, E);
    int nb = (Nn + 1023) / 1024;
    k_scan1<<<nb, 1024>>>(Nn);
    k_scan2<<<1, 32>>>(nb);
    k_scan3<<<(Nn + 255) / 256, 256>>>(Nn, tot);
    k_scatter<<<(tot + 255) / 256, 256>>>(ei, E, Nn);

    for (int b = 0; b < 3; b++) {
        const float* xc = (b == 0) ? x : (const float*)out;
        k_ln<<<(Nn + 7) / 8, 256>>>(xc, gamma + b * DD, beta + b * DD, Nn);
        dim3 gg((Nn + 127) / 128, 2);
        k_gemm<<<gg, 256>>>(W + b * DD * HH * CC, Nn);
        k_alpha<<<(Nn + 7) / 8, 256>>>(att_src + b * HH * CC, att_dst + b * HH * CC, Nn);
        k_agg<<<(Nn + 7) / 8, 256>>>(bias + b * CC, xc, out, Nn);
    }
}

// round 3
// speedup vs baseline: 1.5533x; 1.5533x over previous
#include <cuda_runtime.h>
#include <cstdint>

#define NN 50000
#define EE 400000
#define DD 128
#define HH 2
#define CC 128
#define TE (EE + NN)

// ---------------- static scratch ----------------
__device__ float  g_xn[NN * DD];          // tf32-rounded relu(layernorm(x))
__device__ float  g_h[NN * HH * CC];      // projected features [N, 256]
__device__ float2 g_asrc[NN];
__device__ float2 g_adst[NN];
__device__ int    g_rowptr[NN + 1];
__device__ int    g_wptr[NN];
__device__ int    g_col[TE];
__device__ int    g_cnt[NN];
__device__ int    g_bsum[64];

__device__ __forceinline__ uint32_t f2tf32(float x) {
    uint32_t r;
    asm("cvt.rna.tf32.f32 %0, %1;" : "=r"(r) : "f"(x));
    return r;
}

// ---------------- CSR build ----------------
__global__ void k_init(int n) {
    int i = blockIdx.x * blockDim.x + threadIdx.x;
    if (i < n) g_cnt[i] = 1;
}
__global__ void k_count(const int* __restrict__ ei, int E) {
    int e = blockIdx.x * blockDim.x + threadIdx.x;
    if (e < E) atomicAdd(&g_cnt[ei[E + e]], 1);
}
__global__ void k_scan1(int n) {
    __shared__ int wsum[32];
    int i = blockIdx.x * 1024 + threadIdx.x;
    int v = (i < n) ? g_cnt[i] : 0;
    int lane = threadIdx.x & 31, w = threadIdx.x >> 5;
    int s = v;
#pragma unroll
    for (int o = 1; o < 32; o <<= 1) {
        int t = __shfl_up_sync(0xffffffffu, s, o);
        if (lane >= o) s += t;
    }
    if (lane == 31) wsum[w] = s;
    __syncthreads();
    if (w == 0) {
        int t = wsum[lane];
#pragma unroll
        for (int o = 1; o < 32; o <<= 1) {
            int u = __shfl_up_sync(0xffffffffu, t, o);
            if (lane >= o) t += u;
        }
        wsum[lane] = t;
    }
    __syncthreads();
    int off  = (w > 0) ? wsum[w - 1] : 0;
    int incl = s + off;
    if (i < n) g_rowptr[i] = incl - v;
    if (threadIdx.x == 1023) g_bsum[blockIdx.x] = incl;
}
__global__ void k_scan2(int nb) {
    __shared__ int ws[2];
    int t = threadIdx.x, lane = t & 31, w = t >> 5;
    int v = (t < nb) ? g_bsum[t] : 0;
    int s = v;
#pragma unroll
    for (int o = 1; o < 32; o <<= 1) {
        int u = __shfl_up_sync(0xffffffffu, s, o);
        if (lane >= o) s += u;
    }
    if (lane == 31) ws[w] = s;
    __syncthreads();
    if (w == 1) s += ws[0];
    if (t < nb) g_bsum[t] = s - v;
}
__global__ void k_scan3(int n, int tot) {
    int i = blockIdx.x * blockDim.x + threadIdx.x;
    if (i < n) {
        int r = g_rowptr[i] + g_bsum[i >> 10];
        g_rowptr[i] = r;
        g_wptr[i]   = r;
    }
    if (i == 0) g_rowptr[n] = tot;
}
__global__ void k_scatter(const int* __restrict__ ei, int E, int n) {
    int e = blockIdx.x * blockDim.x + threadIdx.x;
    int tot = E + n;
    if (e >= tot) return;
    int s, d;
    if (e < E) { s = ei[e]; d = ei[E + e]; }
    else       { s = e - E; d = s; }
    int p = atomicAdd(&g_wptr[d], 1);
    g_col[p] = s;
}

// ---------------- LayerNorm + ReLU + tf32 round (warp per row) ----------------
__global__ void k_ln(const float* __restrict__ x, const float* __restrict__ gamma,
                     const float* __restrict__ beta, int n) {
    int row = blockIdx.x * 8 + (threadIdx.x >> 5);
    if (row >= n) return;
    int lane = threadIdx.x & 31;
    float4 v = *reinterpret_cast<const float4*>(&x[row * DD + lane * 4]);
    float s = v.x + v.y + v.z + v.w;
    float q = v.x * v.x + v.y * v.y + v.z * v.z + v.w * v.w;
#pragma unroll
    for (int o = 16; o > 0; o >>= 1) {
        s += __shfl_xor_sync(0xffffffffu, s, o);
        q += __shfl_xor_sync(0xffffffffu, q, o);
    }
    float mu  = s * (1.0f / DD);
    float var = q * (1.0f / DD) - mu * mu;
    float rs  = rsqrtf(var + 1e-5f);
    float4 g = *reinterpret_cast<const float4*>(&gamma[lane * 4]);
    float4 b = *reinterpret_cast<const float4*>(&beta[lane * 4]);
    uint4 o4;
    o4.x = f2tf32(fmaxf(0.f, (v.x - mu) * rs * g.x + b.x));
    o4.y = f2tf32(fmaxf(0.f, (v.y - mu) * rs * g.y + b.y));
    o4.z = f2tf32(fmaxf(0.f, (v.z - mu) * rs * g.z + b.z));
    o4.w = f2tf32(fmaxf(0.f, (v.w - mu) * rs * g.w + b.w));
    *reinterpret_cast<uint4*>(&g_xn[row * DD + lane * 4]) = o4;
}

// ---------------- tf32 mma.sync GEMM ----------------
// g_h = g_xn @ W.  Block tile 128(M) x 128(N), full K=128 in SMEM.
// 8 warps: (w&3) -> M quadrant of 32 rows, (w>>2) -> N half of 64 cols.
// Warp tile 32x64 via m16n8k8: 2 m-tiles x 8 n-tiles.
#define APAD 132
#define BPAD 136
#define AS_FLOATS (128 * APAD)
#define BS_FLOATS (128 * BPAD)
#define GEMM_SMEM ((AS_FLOATS + BS_FLOATS) * 4)

__device__ __forceinline__ void mma_tf32(float* c, const uint32_t* a, const uint32_t* b) {
    asm volatile(
        "mma.sync.aligned.m16n8k8.row.col.f32.tf32.tf32.f32 "
        "{%0,%1,%2,%3}, {%4,%5,%6,%7}, {%8,%9}, {%0,%1,%2,%3};"
        : "+f"(c[0]), "+f"(c[1]), "+f"(c[2]), "+f"(c[3])
        : "r"(a[0]), "r"(a[1]), "r"(a[2]), "r"(a[3]), "r"(b[0]), "r"(b[1]));
}

__global__ __launch_bounds__(256, 1) void k_gemm(const float* __restrict__ W, int M) {
    extern __shared__ float smf[];
    float* As = smf;                 // [row][k]  stride APAD
    float* Bs = smf + AS_FLOATS;     // [k][n]    stride BPAD

    int tid = threadIdx.x;
    int row0 = blockIdx.x * 128;
    int col0 = blockIdx.y * 128;

    // stage A (g_xn already tf32-rounded)
#pragma unroll 4
    for (int i = 0; i < 16; i++) {
        int idx = i * 256 + tid;           // float4 slot
        int r = idx >> 5, c4 = idx & 31;
        int gr = row0 + r; if (gr >= M) gr = M - 1;
        float4 v = *reinterpret_cast<const float4*>(&g_xn[gr * DD + c4 * 4]);
        *reinterpret_cast<float4*>(&As[r * APAD + c4 * 4]) = v;
    }
    // stage B with tf32 rounding
#pragma unroll 4
    for (int i = 0; i < 16; i++) {
        int idx = i * 256 + tid;
        int k = idx >> 5, c4 = idx & 31;
        float4 v = *reinterpret_cast<const float4*>(&W[k * 256 + col0 + c4 * 4]);
        uint4 u;
        u.x = f2tf32(v.x); u.y = f2tf32(v.y); u.z = f2tf32(v.z); u.w = f2tf32(v.w);
        *reinterpret_cast<uint4*>(&Bs[k * BPAD + c4 * 4]) = u;
    }
    __syncthreads();

    int lane = tid & 31;
    int g = lane >> 2, t = lane & 3;
    int arow = (tid >> 5) & 3;  arow *= 32;
    int bcol = (tid >> 7) * 64;

    float acc[2][8][4];
#pragma unroll
    for (int mt = 0; mt < 2; mt++)
#pragma unroll
        for (int nt = 0; nt < 8; nt++)
#pragma unroll
            for (int r = 0; r < 4; r++) acc[mt][nt][r] = 0.f;

#pragma unroll
    for (int kt = 0; kt < 16; kt++) {
        int k0 = kt * 8;
        uint32_t a[2][4], b[8][2];
#pragma unroll
        for (int mt = 0; mt < 2; mt++) {
            int r = arow + mt * 16;
            a[mt][0] = __float_as_uint(As[(r + g)     * APAD + k0 + t]);
            a[mt][1] = __float_as_uint(As[(r + g + 8) * APAD + k0 + t]);
            a[mt][2] = __float_as_uint(As[(r + g)     * APAD + k0 + t + 4]);
            a[mt][3] = __float_as_uint(As[(r + g + 8) * APAD + k0 + t + 4]);
        }
#pragma unroll
        for (int nt = 0; nt < 8; nt++) {
            int c = bcol + nt * 8 + g;
            b[nt][0] = __float_as_uint(Bs[(k0 + t)     * BPAD + c]);
            b[nt][1] = __float_as_uint(Bs[(k0 + t + 4) * BPAD + c]);
        }
#pragma unroll
        for (int mt = 0; mt < 2; mt++)
#pragma unroll
            for (int nt = 0; nt < 8; nt++)
                mma_tf32(acc[mt][nt], a[mt], b[nt]);
    }

    // epilogue: write g_h
#pragma unroll
    for (int mt = 0; mt < 2; mt++) {
        int r0 = row0 + arow + mt * 16 + g;
#pragma unroll
        for (int nt = 0; nt < 8; nt++) {
            int gcol = col0 + bcol + nt * 8 + 2 * t;
            if (r0 < M)
                *reinterpret_cast<float2*>(&g_h[r0 * 256 + gcol]) =
                    make_float2(acc[mt][nt][0], acc[mt][nt][1]);
            if (r0 + 8 < M)
                *reinterpret_cast<float2*>(&g_h[(r0 + 8) * 256 + gcol]) =
                    make_float2(acc[mt][nt][2], acc[mt][nt][3]);
        }
    }
}

// ---------------- attention coefficients (warp per row) ----------------
__global__ void k_alpha(const float* __restrict__ as_, const float* __restrict__ ad_, int n) {
    int row = blockIdx.x * 8 + (threadIdx.x >> 5);
    if (row >= n) return;
    int lane = threadIdx.x & 31;
    float4 h0 = *reinterpret_cast<const float4*>(&g_h[row * 256 + lane * 4]);
    float4 h1 = *reinterpret_cast<const float4*>(&g_h[row * 256 + 128 + lane * 4]);
    float4 a0 = *reinterpret_cast<const float4*>(&as_[lane * 4]);
    float4 a1 = *reinterpret_cast<const float4*>(&as_[128 + lane * 4]);
    float4 d0 = *reinterpret_cast<const float4*>(&ad_[lane * 4]);
    float4 d1 = *reinterpret_cast<const float4*>(&ad_[128 + lane * 4]);
    float s0 = h0.x * a0.x + h0.y * a0.y + h0.z * a0.z + h0.w * a0.w;
    float s1 = h1.x * a1.x + h1.y * a1.y + h1.z * a1.z + h1.w * a1.w;
    float t0 = h0.x * d0.x + h0.y * d0.y + h0.z * d0.z + h0.w * d0.w;
    float t1 = h1.x * d1.x + h1.y * d1.y + h1.z * d1.z + h1.w * d1.w;
#pragma unroll
    for (int o = 16; o > 0; o >>= 1) {
        s0 += __shfl_xor_sync(0xffffffffu, s0, o);
        s1 += __shfl_xor_sync(0xffffffffu, s1, o);
        t0 += __shfl_xor_sync(0xffffffffu, t0, o);
        t1 += __shfl_xor_sync(0xffffffffu, t1, o);
    }
    if (lane == 0) {
        g_asrc[row] = make_float2(s0, s1);
        g_adst[row] = make_float2(t0, t1);
    }
}

// ---------------- fused segment softmax + aggregation (warp per dst node) -------
__global__ void k_agg(const float* __restrict__ bias, const float* __restrict__ resid,
                      float* __restrict__ out, int n) {
    int node = blockIdx.x * 8 + (threadIdx.x >> 5);
    if (node >= n) return;
    int lane = threadIdx.x & 31;
    int s = g_rowptr[node], t = g_rowptr[node + 1];
    float2 ad = g_adst[node];

    float m0 = -1e30f, m1 = -1e30f;
    for (int e = s + lane; e < t; e += 32) {
        float2 as = g_asrc[g_col[e]];
        float e0 = as.x + ad.x; e0 = e0 > 0.f ? e0 : 0.2f * e0;
        float e1 = as.y + ad.y; e1 = e1 > 0.f ? e1 : 0.2f * e1;
        m0 = fmaxf(m0, e0); m1 = fmaxf(m1, e1);
    }
#pragma unroll
    for (int o = 16; o > 0; o >>= 1) {
        m0 = fmaxf(m0, __shfl_xor_sync(0xffffffffu, m0, o));
        m1 = fmaxf(m1, __shfl_xor_sync(0xffffffffu, m1, o));
    }

    float4 a0 = make_float4(0.f, 0.f, 0.f, 0.f), a1 = a0;
    float s0 = 0.f, s1 = 0.f;
    for (int e = s; e < t; e++) {
        int c = g_col[e];
        float2 as = g_asrc[c];
        float e0 = as.x + ad.x; e0 = e0 > 0.f ? e0 : 0.2f * e0;
        float e1 = as.y + ad.y; e1 = e1 > 0.f ? e1 : 0.2f * e1;
        float w0 = __expf(e0 - m0), w1 = __expf(e1 - m1);
        s0 += w0; s1 += w1;
        float4 h0 = *reinterpret_cast<const float4*>(&g_h[c * 256 + lane * 4]);
        float4 h1 = *reinterpret_cast<const float4*>(&g_h[c * 256 + 128 + lane * 4]);
        a0.x += h0.x * w0; a0.y += h0.y * w0; a0.z += h0.z * w0; a0.w += h0.w * w0;
        a1.x += h1.x * w1; a1.y += h1.y * w1; a1.z += h1.z * w1; a1.w += h1.w * w1;
    }
    float i0 = 0.5f / (s0 + 1e-16f);
    float i1 = 0.5f / (s1 + 1e-16f);
    float4 bb = *reinterpret_cast<const float4*>(&bias[lane * 4]);
    float4 rr = *reinterpret_cast<const float4*>(&resid[node * DD + lane * 4]);
    float4 o4;
    o4.x = a0.x * i0 + a1.x * i1 + bb.x + rr.x;
    o4.y = a0.y * i0 + a1.y * i1 + bb.y + rr.y;
    o4.z = a0.z * i0 + a1.z * i1 + bb.z + rr.z;
    o4.w = a0.w * i0 + a1.w * i1 + bb.w + rr.w;
    *reinterpret_cast<float4*>(&out[node * DD + lane * 4]) = o4;
}

// ---------------- launch ----------------
extern "C" void kernel_launch(void* const* d_in, const int* in_sizes, int n_in,
                              void* d_out, int out_size) {
    const float* x       = (const float*)d_in[0];
    const int*   ei      = (const int*)d_in[1];
    const float* W       = (const float*)d_in[2];
    const float* att_src = (const float*)d_in[3];
    const float* att_dst = (const float*)d_in[4];
    const float* bias    = (const float*)d_in[5];
    const float* gamma   = (const float*)d_in[6];
    const float* beta    = (const float*)d_in[7];
    float* out = (float*)d_out;

    int Nn  = in_sizes[0] / DD;
    int E   = in_sizes[1] / 2;
    int tot = E + Nn;

    cudaFuncSetAttribute(k_gemm, cudaFuncAttributeMaxDynamicSharedMemorySize, GEMM_SMEM);

    k_init<<<(Nn + 255) / 256, 256>>>(Nn);
    k_count<<<(E + 255) / 256, 256>>>(ei, E);
    int nb = (Nn + 1023) / 1024;
    k_scan1<<<nb, 1024>>>(Nn);
    k_scan2<<<1, 64>>>(nb);
    k_scan3<<<(Nn + 255) / 256, 256>>>(Nn, tot);
    k_scatter<<<(tot + 255) / 256, 256>>>(ei, E, Nn);

    for (int b = 0; b < 3; b++) {
        const float* xc = (b == 0) ? x : (const float*)out;
        k_ln<<<(Nn + 7) / 8, 256>>>(xc, gamma + b * DD, beta + b * DD, Nn);
        dim3 gg((Nn + 127) / 128, 2);
        k_gemm<<<gg, 256, GEMM_SMEM>>>(W + b * DD * HH * CC, Nn);
        k_alpha<<<(Nn + 7) / 8, 256>>>(att_src + b * HH * CC, att_dst + b * HH * CC, Nn);
        k_agg<<<(Nn + 7) / 8, 256>>>(bias + b * CC, xc, out, Nn);
    }
}

// round 4
// speedup vs baseline: 1.7161x; 1.1048x over previous
#include <cuda_runtime.h>
#include <cstdint>

#define NN 50000
#define EE 400000
#define DD 128
#define HH 2
#define CC 128
#define TE (EE + NN)

// ---------------- static scratch ----------------
__device__ float  g_xn[NN * DD];          // tf32-rounded relu(layernorm(x))
__device__ float  g_h[NN * HH * CC];      // projected features [N, 256]
__device__ float  g_as[2][NN * HH];       // alpha_src, double-buffered [node*2+head]
__device__ float  g_ad[2][NN * HH];       // alpha_dst
__device__ int    g_rowptr[NN + 1];
__device__ int    g_wptr[NN];
__device__ int    g_col[TE];
__device__ int    g_cnt[NN];
__device__ int    g_bsum[64];

__device__ __forceinline__ uint32_t f2tf32(float x) {
    uint32_t r;
    asm("cvt.rna.tf32.f32 %0, %1;" : "=r"(r) : "f"(x));
    return r;
}

// ---------------- CSR build ----------------
__global__ void k_init(int n) {
    int i = blockIdx.x * blockDim.x + threadIdx.x;
    if (i < n) g_cnt[i] = 1;
}
__global__ void k_count(const int* __restrict__ ei, int E) {
    int e = blockIdx.x * blockDim.x + threadIdx.x;
    if (e < E) atomicAdd(&g_cnt[ei[E + e]], 1);
}
__global__ void k_scan1(int n) {
    __shared__ int wsum[32];
    int i = blockIdx.x * 1024 + threadIdx.x;
    int v = (i < n) ? g_cnt[i] : 0;
    int lane = threadIdx.x & 31, w = threadIdx.x >> 5;
    int s = v;
#pragma unroll
    for (int o = 1; o < 32; o <<= 1) {
        int t = __shfl_up_sync(0xffffffffu, s, o);
        if (lane >= o) s += t;
    }
    if (lane == 31) wsum[w] = s;
    __syncthreads();
    if (w == 0) {
        int t = wsum[lane];
#pragma unroll
        for (int o = 1; o < 32; o <<= 1) {
            int u = __shfl_up_sync(0xffffffffu, t, o);
            if (lane >= o) t += u;
        }
        wsum[lane] = t;
    }
    __syncthreads();
    int off  = (w > 0) ? wsum[w - 1] : 0;
    int incl = s + off;
    if (i < n) g_rowptr[i] = incl - v;              // exclusive within block
    if (threadIdx.x == 1023) g_bsum[blockIdx.x] = incl;   // block total
}
// scan3 with fused cross-block prefix (2 threads serially sum <=49 block totals)
__global__ void k_scan3(int n, int tot) {
    __shared__ int pfx[2];
    int base = blockIdx.x * 256;
    if (threadIdx.x < 2) {
        int idx = base + (int)threadIdx.x * 255;
        if (idx >= n) idx = n - 1;
        int chunk = idx >> 10;
        int acc = 0;
        for (int j = 0; j < chunk; j++) acc += g_bsum[j];
        pfx[threadIdx.x] = acc;
    }
    __syncthreads();
    int i = base + threadIdx.x;
    if (i < n) {
        int sel = ((i >> 10) != (base >> 10)) ? 1 : 0;
        int r = g_rowptr[i] + pfx[sel];
        g_rowptr[i] = r;
        g_wptr[i]   = r;
    }
    if (i == 0) g_rowptr[n] = tot;
}
__global__ void k_scatter(const int* __restrict__ ei, int E, int n) {
    int e = blockIdx.x * blockDim.x + threadIdx.x;
    int tot = E + n;
    if (e >= tot) return;
    int s, d;
    if (e < E) { s = ei[e]; d = ei[E + e]; }
    else       { s = e - E; d = s; }
    int p = atomicAdd(&g_wptr[d], 1);
    g_col[p] = s;
}

// ---------------- LayerNorm + ReLU + tf32 round (block 0 only) ----------------
__global__ void k_ln(const float* __restrict__ x, const float* __restrict__ gamma,
                     const float* __restrict__ beta, int n) {
    int row = blockIdx.x * 8 + (threadIdx.x >> 5);
    if (row >= n) return;
    int lane = threadIdx.x & 31;
    float4 v = *reinterpret_cast<const float4*>(&x[row * DD + lane * 4]);
    float s = v.x + v.y + v.z + v.w;
    float q = v.x * v.x + v.y * v.y + v.z * v.z + v.w * v.w;
#pragma unroll
    for (int o = 16; o > 0; o >>= 1) {
        s += __shfl_xor_sync(0xffffffffu, s, o);
        q += __shfl_xor_sync(0xffffffffu, q, o);
    }
    float mu  = s * (1.0f / DD);
    float var = q * (1.0f / DD) - mu * mu;
    float rs  = rsqrtf(var + 1e-5f);
    float4 g = *reinterpret_cast<const float4*>(&gamma[lane * 4]);
    float4 b = *reinterpret_cast<const float4*>(&beta[lane * 4]);
    uint4 o4;
    o4.x = f2tf32(fmaxf(0.f, (v.x - mu) * rs * g.x + b.x));
    o4.y = f2tf32(fmaxf(0.f, (v.y - mu) * rs * g.y + b.y));
    o4.z = f2tf32(fmaxf(0.f, (v.z - mu) * rs * g.z + b.z));
    o4.w = f2tf32(fmaxf(0.f, (v.w - mu) * rs * g.w + b.w));
    *reinterpret_cast<uint4*>(&g_xn[row * DD + lane * 4]) = o4;
    if (lane == 0) {   // zero alpha accumulators for buffer 0 (block 0 GEMM)
        *reinterpret_cast<float2*>(&g_as[0][row * 2]) = make_float2(0.f, 0.f);
        *reinterpret_cast<float2*>(&g_ad[0][row * 2]) = make_float2(0.f, 0.f);
    }
}

// ---------------- tf32 mma.sync GEMM + fused alpha dot-products ----------------
#define APAD 132
#define BPAD 136
#define AS_FLOATS (128 * APAD)
#define BS_FLOATS (128 * BPAD)
#define GEMM_SMEM ((AS_FLOATS + BS_FLOATS) * 4)

__device__ __forceinline__ void mma_tf32(float* c, const uint32_t* a, const uint32_t* b) {
    asm volatile(
        "mma.sync.aligned.m16n8k8.row.col.f32.tf32.tf32.f32 "
        "{%0,%1,%2,%3}, {%4,%5,%6,%7}, {%8,%9}, {%0,%1,%2,%3};"
        : "+f"(c[0]), "+f"(c[1]), "+f"(c[2]), "+f"(c[3])
        : "r"(a[0]), "r"(a[1]), "r"(a[2]), "r"(a[3]), "r"(b[0]), "r"(b[1]));
}

__global__ __launch_bounds__(256, 1) void k_gemm(const float* __restrict__ W,
                                                 const float* __restrict__ as_,
                                                 const float* __restrict__ ad_,
                                                 int buf, int M) {
    extern __shared__ float smf[];
    float* As = smf;                 // [row][k]  stride APAD
    float* Bs = smf + AS_FLOATS;     // [k][n]    stride BPAD

    int tid = threadIdx.x;
    int row0 = blockIdx.x * 128;
    int col0 = blockIdx.y * 128;

#pragma unroll 4
    for (int i = 0; i < 16; i++) {
        int idx = i * 256 + tid;
        int r = idx >> 5, c4 = idx & 31;
        int gr = row0 + r; if (gr >= M) gr = M - 1;
        float4 v = *reinterpret_cast<const float4*>(&g_xn[gr * DD + c4 * 4]);
        *reinterpret_cast<float4*>(&As[r * APAD + c4 * 4]) = v;
    }
#pragma unroll 4
    for (int i = 0; i < 16; i++) {
        int idx = i * 256 + tid;
        int k = idx >> 5, c4 = idx & 31;
        float4 v = *reinterpret_cast<const float4*>(&W[k * 256 + col0 + c4 * 4]);
        uint4 u;
        u.x = f2tf32(v.x); u.y = f2tf32(v.y); u.z = f2tf32(v.z); u.w = f2tf32(v.w);
        *reinterpret_cast<uint4*>(&Bs[k * BPAD + c4 * 4]) = u;
    }
    __syncthreads();

    int lane = tid & 31;
    int g = lane >> 2, t = lane & 3;
    int arow = ((tid >> 5) & 3) * 32;
    int bcol = (tid >> 7) * 64;

    float acc[2][8][4];
#pragma unroll
    for (int mt = 0; mt < 2; mt++)
#pragma unroll
        for (int nt = 0; nt < 8; nt++)
#pragma unroll
            for (int r = 0; r < 4; r++) acc[mt][nt][r] = 0.f;

#pragma unroll
    for (int kt = 0; kt < 16; kt++) {
        int k0 = kt * 8;
        uint32_t a[2][4], b[8][2];
#pragma unroll
        for (int mt = 0; mt < 2; mt++) {
            int r = arow + mt * 16;
            a[mt][0] = __float_as_uint(As[(r + g)     * APAD + k0 + t]);
            a[mt][1] = __float_as_uint(As[(r + g + 8) * APAD + k0 + t]);
            a[mt][2] = __float_as_uint(As[(r + g)     * APAD + k0 + t + 4]);
            a[mt][3] = __float_as_uint(As[(r + g + 8) * APAD + k0 + t + 4]);
        }
#pragma unroll
        for (int nt = 0; nt < 8; nt++) {
            int c = bcol + nt * 8 + g;
            b[nt][0] = __float_as_uint(Bs[(k0 + t)     * BPAD + c]);
            b[nt][1] = __float_as_uint(Bs[(k0 + t + 4) * BPAD + c]);
        }
#pragma unroll
        for (int mt = 0; mt < 2; mt++)
#pragma unroll
            for (int nt = 0; nt < 8; nt++)
                mma_tf32(acc[mt][nt], a[mt], b[nt]);
    }

    // store g_h
#pragma unroll
    for (int mt = 0; mt < 2; mt++) {
        int r0 = row0 + arow + mt * 16 + g;
#pragma unroll
        for (int nt = 0; nt < 8; nt++) {
            int gcol = col0 + bcol + nt * 8 + 2 * t;
            if (r0 < M)
                *reinterpret_cast<float2*>(&g_h[r0 * 256 + gcol]) =
                    make_float2(acc[mt][nt][0], acc[mt][nt][1]);
            if (r0 + 8 < M)
                *reinterpret_cast<float2*>(&g_h[(r0 + 8) * 256 + gcol]) =
                    make_float2(acc[mt][nt][2], acc[mt][nt][3]);
        }
    }

    // fused alpha dot-products (head = blockIdx.y, cols are local to this half)
    {
        const float* asg = as_ + col0;
        const float* adg = ad_ + col0;
        float dS[4] = {0.f, 0.f, 0.f, 0.f}, dD[4] = {0.f, 0.f, 0.f, 0.f};
#pragma unroll
        for (int nt = 0; nt < 8; nt++) {
            int c = bcol + nt * 8 + 2 * t;
            float a0v = __ldg(&asg[c]), a1v = __ldg(&asg[c + 1]);
            float d0v = __ldg(&adg[c]), d1v = __ldg(&adg[c + 1]);
#pragma unroll
            for (int mt = 0; mt < 2; mt++) {
                dS[mt * 2 + 0] += acc[mt][nt][0] * a0v + acc[mt][nt][1] * a1v;
                dS[mt * 2 + 1] += acc[mt][nt][2] * a0v + acc[mt][nt][3] * a1v;
                dD[mt * 2 + 0] += acc[mt][nt][0] * d0v + acc[mt][nt][1] * d1v;
                dD[mt * 2 + 1] += acc[mt][nt][2] * d0v + acc[mt][nt][3] * d1v;
            }
        }
#pragma unroll
        for (int q = 0; q < 4; q++) {
            dS[q] += __shfl_xor_sync(0xffffffffu, dS[q], 1);
            dS[q] += __shfl_xor_sync(0xffffffffu, dS[q], 2);
            dD[q] += __shfl_xor_sync(0xffffffffu, dD[q], 1);
            dD[q] += __shfl_xor_sync(0xffffffffu, dD[q], 2);
        }
        if (t == 0) {
            int head = blockIdx.y;
#pragma unroll
            for (int q = 0; q < 4; q++) {
                int r = row0 + arow + (q >> 1) * 16 + g + (q & 1) * 8;
                if (r < M) {
                    atomicAdd(&g_as[buf][r * 2 + head], dS[q]);
                    atomicAdd(&g_ad[buf][r * 2 + head], dD[q]);
                }
            }
        }
    }
}

// ------- fused softmax+aggregation (+ optional LN of next block) -------
__global__ void k_agg(const float* __restrict__ bias, const float* __restrict__ resid,
                      float* __restrict__ out, int n, int buf,
                      const float* __restrict__ gn, const float* __restrict__ bn,
                      int do_ln) {
    int node = blockIdx.x * 8 + (threadIdx.x >> 5);
    if (node >= n) return;
    int lane = threadIdx.x & 31;
    int s = g_rowptr[node], t = g_rowptr[node + 1];
    float2 ad = *reinterpret_cast<const float2*>(&g_ad[buf][node * 2]);

    float4 a0 = make_float4(0.f, 0.f, 0.f, 0.f), a1 = a0;
    float s0 = 0.f, s1 = 0.f;
#pragma unroll 2
    for (int e = s; e < t; e++) {
        int c = g_col[e];
        float2 as = *reinterpret_cast<const float2*>(&g_as[buf][c * 2]);
        float e0 = as.x + ad.x; e0 = e0 > 0.f ? e0 : 0.2f * e0;
        float e1 = as.y + ad.y; e1 = e1 > 0.f ? e1 : 0.2f * e1;
        float w0 = __expf(e0), w1 = __expf(e1);
        s0 += w0; s1 += w1;
        float4 h0 = *reinterpret_cast<const float4*>(&g_h[c * 256 + lane * 4]);
        float4 h1 = *reinterpret_cast<const float4*>(&g_h[c * 256 + 128 + lane * 4]);
        a0.x += h0.x * w0; a0.y += h0.y * w0; a0.z += h0.z * w0; a0.w += h0.w * w0;
        a1.x += h1.x * w1; a1.y += h1.y * w1; a1.z += h1.z * w1; a1.w += h1.w * w1;
    }
    float i0 = 0.5f / (s0 + 1e-16f);
    float i1 = 0.5f / (s1 + 1e-16f);
    float4 bb = *reinterpret_cast<const float4*>(&bias[lane * 4]);
    float4 rr = *reinterpret_cast<const float4*>(&resid[node * DD + lane * 4]);
    float4 o4;
    o4.x = a0.x * i0 + a1.x * i1 + bb.x + rr.x;
    o4.y = a0.y * i0 + a1.y * i1 + bb.y + rr.y;
    o4.z = a0.z * i0 + a1.z * i1 + bb.z + rr.z;
    o4.w = a0.w * i0 + a1.w * i1 + bb.w + rr.w;
    *reinterpret_cast<float4*>(&out[node * DD + lane * 4]) = o4;

    // zero alpha accumulators of the other buffer for the next block's GEMM
    if (lane == 0) {
        *reinterpret_cast<float2*>(&g_as[buf ^ 1][node * 2]) = make_float2(0.f, 0.f);
        *reinterpret_cast<float2*>(&g_ad[buf ^ 1][node * 2]) = make_float2(0.f, 0.f);
    }

    if (do_ln) {   // LN+ReLU+tf32 of this freshly produced row for next block
        float ss = o4.x + o4.y + o4.z + o4.w;
        float qq = o4.x * o4.x + o4.y * o4.y + o4.z * o4.z + o4.w * o4.w;
#pragma unroll
        for (int o = 16; o > 0; o >>= 1) {
            ss += __shfl_xor_sync(0xffffffffu, ss, o);
            qq += __shfl_xor_sync(0xffffffffu, qq, o);
        }
        float mu  = ss * (1.0f / DD);
        float var = qq * (1.0f / DD) - mu * mu;
        float rs  = rsqrtf(var + 1e-5f);
        float4 g4 = *reinterpret_cast<const float4*>(&gn[lane * 4]);
        float4 b4 = *reinterpret_cast<const float4*>(&bn[lane * 4]);
        uint4 u;
        u.x = f2tf32(fmaxf(0.f, (o4.x - mu) * rs * g4.x + b4.x));
        u.y = f2tf32(fmaxf(0.f, (o4.y - mu) * rs * g4.y + b4.y));
        u.z = f2tf32(fmaxf(0.f, (o4.z - mu) * rs * g4.z + b4.z));
        u.w = f2tf32(fmaxf(0.f, (o4.w - mu) * rs * g4.w + b4.w));
        *reinterpret_cast<uint4*>(&g_xn[node * DD + lane * 4]) = u;
    }
}

// ---------------- launch ----------------
extern "C" void kernel_launch(void* const* d_in, const int* in_sizes, int n_in,
                              void* d_out, int out_size) {
    const float* x       = (const float*)d_in[0];
    const int*   ei      = (const int*)d_in[1];
    const float* W       = (const float*)d_in[2];
    const float* att_src = (const float*)d_in[3];
    const float* att_dst = (const float*)d_in[4];
    const float* bias    = (const float*)d_in[5];
    const float* gamma   = (const float*)d_in[6];
    const float* beta    = (const float*)d_in[7];
    float* out = (float*)d_out;

    int Nn  = in_sizes[0] / DD;
    int E   = in_sizes[1] / 2;
    int tot = E + Nn;

    cudaFuncSetAttribute(k_gemm, cudaFuncAttributeMaxDynamicSharedMemorySize, GEMM_SMEM);

    k_init<<<(Nn + 255) / 256, 256>>>(Nn);
    k_count<<<(E + 255) / 256, 256>>>(ei, E);
    k_scan1<<<(Nn + 1023) / 1024, 1024>>>(Nn);
    k_scan3<<<(Nn + 255) / 256, 256>>>(Nn, tot);
    k_scatter<<<(tot + 255) / 256, 256>>>(ei, E, Nn);

    k_ln<<<(Nn + 7) / 8, 256>>>(x, gamma, beta, Nn);

    for (int b = 0; b < 3; b++) {
        const float* xc = (b == 0) ? x : (const float*)out;
        int buf = b & 1;
        dim3 gg((Nn + 127) / 128, 2);
        k_gemm<<<gg, 256, GEMM_SMEM>>>(W + b * DD * HH * CC,
                                       att_src + b * HH * CC, att_dst + b * HH * CC,
                                       buf, Nn);
        int do_ln = (b < 2) ? 1 : 0;
        const float* gn = gamma + (b + 1 < 3 ? (b + 1) * DD : 0);
        const float* bn = beta  + (b + 1 < 3 ? (b + 1) * DD : 0);
        k_agg<<<(Nn + 7) / 8, 256>>>(bias + b * CC, xc, out, Nn, buf, gn, bn, do_ln);
    }
}

// round 5
// speedup vs baseline: 1.8266x; 1.0644x over previous
#include <cuda_runtime.h>
#include <cuda_bf16.h>
#include <cstdint>

#define NN 50000
#define EE 400000
#define DD 128
#define HH 2
#define CC 128
#define TE (EE + NN)

// ---------------- static scratch ----------------
__device__ float  g_xn[NN * DD];                 // tf32-rounded relu(layernorm(x))
__device__ __nv_bfloat16 g_h[NN * HH * CC];      // messages, lane-interleaved bf16
__device__ float  g_as[2][NN * HH];              // alpha_src (double-buffered)
__device__ float  g_ad[2][NN * HH];              // alpha_dst
__device__ int    g_rowptr[NN + 1];
__device__ int    g_wptr[NN];
__device__ int    g_col[TE];
__device__ int    g_cnt[NN];
__device__ int    g_bsum[64];

__device__ __forceinline__ uint32_t f2tf32(float x) {
    uint32_t r;
    asm("cvt.rna.tf32.f32 %0, %1;" : "=r"(r) : "f"(x));
    return r;
}

// ---------------- CSR build ----------------
__global__ void k_init(int n) {
    int i = blockIdx.x * blockDim.x + threadIdx.x;
    if (i < n) g_cnt[i] = 1;
}
__global__ void k_count(const int* __restrict__ ei, int E) {
    int e = blockIdx.x * blockDim.x + threadIdx.x;
    if (e < E) atomicAdd(&g_cnt[ei[E + e]], 1);
}
__global__ void k_scan1(int n) {
    __shared__ int wsum[32];
    int i = blockIdx.x * 1024 + threadIdx.x;
    int v = (i < n) ? g_cnt[i] : 0;
    int lane = threadIdx.x & 31, w = threadIdx.x >> 5;
    int s = v;
#pragma unroll
    for (int o = 1; o < 32; o <<= 1) {
        int t = __shfl_up_sync(0xffffffffu, s, o);
        if (lane >= o) s += t;
    }
    if (lane == 31) wsum[w] = s;
    __syncthreads();
    if (w == 0) {
        int t = wsum[lane];
#pragma unroll
        for (int o = 1; o < 32; o <<= 1) {
            int u = __shfl_up_sync(0xffffffffu, t, o);
            if (lane >= o) t += u;
        }
        wsum[lane] = t;
    }
    __syncthreads();
    int off  = (w > 0) ? wsum[w - 1] : 0;
    int incl = s + off;
    if (i < n) g_rowptr[i] = incl - v;
    if (threadIdx.x == 1023) g_bsum[blockIdx.x] = incl;
}
__global__ void k_scan3(int n, int tot) {
    __shared__ int pfx[2];
    int base = blockIdx.x * 256;
    if (threadIdx.x < 2) {
        int idx = base + (int)threadIdx.x * 255;
        if (idx >= n) idx = n - 1;
        int chunk = idx >> 10;
        int acc = 0;
        for (int j = 0; j < chunk; j++) acc += g_bsum[j];
        pfx[threadIdx.x] = acc;
    }
    __syncthreads();
    int i = base + threadIdx.x;
    if (i < n) {
        int sel = ((i >> 10) != (base >> 10)) ? 1 : 0;
        int r = g_rowptr[i] + pfx[sel];
        g_rowptr[i] = r;
        g_wptr[i]   = r;
    }
    if (i == 0) g_rowptr[n] = tot;
}
__global__ void k_scatter(const int* __restrict__ ei, int E, int n) {
    int e = blockIdx.x * blockDim.x + threadIdx.x;
    int tot = E + n;
    if (e >= tot) return;
    int s, d;
    if (e < E) { s = ei[e]; d = ei[E + e]; }
    else       { s = e - E; d = s; }
    int p = atomicAdd(&g_wptr[d], 1);
    g_col[p] = s;
}

// ---------------- LayerNorm + ReLU + tf32 round (block 0 only) ----------------
__global__ void k_ln(const float* __restrict__ x, const float* __restrict__ gamma,
                     const float* __restrict__ beta, int n) {
    int row = blockIdx.x * 8 + (threadIdx.x >> 5);
    if (row >= n) return;
    int lane = threadIdx.x & 31;
    float4 v = *reinterpret_cast<const float4*>(&x[row * DD + lane * 4]);
    float s = v.x + v.y + v.z + v.w;
    float q = v.x * v.x + v.y * v.y + v.z * v.z + v.w * v.w;
#pragma unroll
    for (int o = 16; o > 0; o >>= 1) {
        s += __shfl_xor_sync(0xffffffffu, s, o);
        q += __shfl_xor_sync(0xffffffffu, q, o);
    }
    float mu  = s * (1.0f / DD);
    float var = q * (1.0f / DD) - mu * mu;
    float rs  = rsqrtf(var + 1e-5f);
    float4 g = *reinterpret_cast<const float4*>(&gamma[lane * 4]);
    float4 b = *reinterpret_cast<const float4*>(&beta[lane * 4]);
    uint4 o4;
    o4.x = f2tf32(fmaxf(0.f, (v.x - mu) * rs * g.x + b.x));
    o4.y = f2tf32(fmaxf(0.f, (v.y - mu) * rs * g.y + b.y));
    o4.z = f2tf32(fmaxf(0.f, (v.z - mu) * rs * g.z + b.z));
    o4.w = f2tf32(fmaxf(0.f, (v.w - mu) * rs * g.w + b.w));
    *reinterpret_cast<uint4*>(&g_xn[row * DD + lane * 4]) = o4;
    if (lane == 0) {
        *reinterpret_cast<float2*>(&g_as[0][row * 2]) = make_float2(0.f, 0.f);
        *reinterpret_cast<float2*>(&g_ad[0][row * 2]) = make_float2(0.f, 0.f);
    }
}

// ---------------- tf32 mma.sync GEMM + fused alpha dot-products ----------------
#define APAD 132
#define BPAD 136
#define AS_FLOATS (128 * APAD)
#define BS_FLOATS (128 * BPAD)
#define GEMM_SMEM ((AS_FLOATS + BS_FLOATS) * 4)

__device__ __forceinline__ void mma_tf32(float* c, const uint32_t* a, const uint32_t* b) {
    asm volatile(
        "mma.sync.aligned.m16n8k8.row.col.f32.tf32.tf32.f32 "
        "{%0,%1,%2,%3}, {%4,%5,%6,%7}, {%8,%9}, {%0,%1,%2,%3};"
        : "+f"(c[0]), "+f"(c[1]), "+f"(c[2]), "+f"(c[3])
        : "r"(a[0]), "r"(a[1]), "r"(a[2]), "r"(a[3]), "r"(b[0]), "r"(b[1]));
}

__global__ __launch_bounds__(256, 1) void k_gemm(const float* __restrict__ W,
                                                 const float* __restrict__ as_,
                                                 const float* __restrict__ ad_,
                                                 int buf, int M) {
    extern __shared__ float smf[];
    float* As = smf;                 // [row][k]  stride APAD
    float* Bs = smf + AS_FLOATS;     // [k][n]    stride BPAD

    int tid = threadIdx.x;
    int row0 = blockIdx.x * 128;
    int col0 = blockIdx.y * 128;

#pragma unroll 4
    for (int i = 0; i < 16; i++) {
        int idx = i * 256 + tid;
        int r = idx >> 5, c4 = idx & 31;
        int gr = row0 + r; if (gr >= M) gr = M - 1;
        float4 v = *reinterpret_cast<const float4*>(&g_xn[gr * DD + c4 * 4]);
        *reinterpret_cast<float4*>(&As[r * APAD + c4 * 4]) = v;
    }
#pragma unroll 4
    for (int i = 0; i < 16; i++) {
        int idx = i * 256 + tid;
        int k = idx >> 5, c4 = idx & 31;
        float4 v = *reinterpret_cast<const float4*>(&W[k * 256 + col0 + c4 * 4]);
        uint4 u;
        u.x = f2tf32(v.x); u.y = f2tf32(v.y); u.z = f2tf32(v.z); u.w = f2tf32(v.w);
        *reinterpret_cast<uint4*>(&Bs[k * BPAD + c4 * 4]) = u;
    }
    __syncthreads();

    int lane = tid & 31;
    int g = lane >> 2, t = lane & 3;
    int arow = ((tid >> 5) & 3) * 32;
    int bcol = (tid >> 7) * 64;

    float acc[2][8][4];
#pragma unroll
    for (int mt = 0; mt < 2; mt++)
#pragma unroll
        for (int nt = 0; nt < 8; nt++)
#pragma unroll
            for (int r = 0; r < 4; r++) acc[mt][nt][r] = 0.f;

#pragma unroll
    for (int kt = 0; kt < 16; kt++) {
        int k0 = kt * 8;
        uint32_t a[2][4], b[8][2];
#pragma unroll
        for (int mt = 0; mt < 2; mt++) {
            int r = arow + mt * 16;
            a[mt][0] = __float_as_uint(As[(r + g)     * APAD + k0 + t]);
            a[mt][1] = __float_as_uint(As[(r + g + 8) * APAD + k0 + t]);
            a[mt][2] = __float_as_uint(As[(r + g)     * APAD + k0 + t + 4]);
            a[mt][3] = __float_as_uint(As[(r + g + 8) * APAD + k0 + t + 4]);
        }
#pragma unroll
        for (int nt = 0; nt < 8; nt++) {
            int c = bcol + nt * 8 + g;
            b[nt][0] = __float_as_uint(Bs[(k0 + t)     * BPAD + c]);
            b[nt][1] = __float_as_uint(Bs[(k0 + t + 4) * BPAD + c]);
        }
#pragma unroll
        for (int mt = 0; mt < 2; mt++)
#pragma unroll
            for (int nt = 0; nt < 8; nt++)
                mma_tf32(acc[mt][nt], a[mt], b[nt]);
    }

    // store g_h as bf16, lane-interleaved: idx = r*256 + (c>>2)*8 + head*4 + (c&3)
    int head = blockIdx.y;
#pragma unroll
    for (int mt = 0; mt < 2; mt++) {
        int r0 = row0 + arow + mt * 16 + g;
#pragma unroll
        for (int nt = 0; nt < 8; nt++) {
            int c = bcol + nt * 8 + 2 * t;      // even, pair (c, c+1) in one quad
            int lidx = (c >> 2) * 8 + head * 4 + (c & 3);
            if (r0 < M) {
                __nv_bfloat162 p = __float22bfloat162_rn(
                    make_float2(acc[mt][nt][0], acc[mt][nt][1]));
                *reinterpret_cast<__nv_bfloat162*>(&g_h[r0 * 256 + lidx]) = p;
            }
            if (r0 + 8 < M) {
                __nv_bfloat162 p = __float22bfloat162_rn(
                    make_float2(acc[mt][nt][2], acc[mt][nt][3]));
                *reinterpret_cast<__nv_bfloat162*>(&g_h[(r0 + 8) * 256 + lidx]) = p;
            }
        }
    }

    // fused alpha dot-products (fp32, from accumulators)
    {
        const float* asg = as_ + col0;
        const float* adg = ad_ + col0;
        float dS[4] = {0.f, 0.f, 0.f, 0.f}, dD[4] = {0.f, 0.f, 0.f, 0.f};
#pragma unroll
        for (int nt = 0; nt < 8; nt++) {
            int c = bcol + nt * 8 + 2 * t;
            float a0v = __ldg(&asg[c]), a1v = __ldg(&asg[c + 1]);
            float d0v = __ldg(&adg[c]), d1v = __ldg(&adg[c + 1]);
#pragma unroll
            for (int mt = 0; mt < 2; mt++) {
                dS[mt * 2 + 0] += acc[mt][nt][0] * a0v + acc[mt][nt][1] * a1v;
                dS[mt * 2 + 1] += acc[mt][nt][2] * a0v + acc[mt][nt][3] * a1v;
                dD[mt * 2 + 0] += acc[mt][nt][0] * d0v + acc[mt][nt][1] * d1v;
                dD[mt * 2 + 1] += acc[mt][nt][2] * d0v + acc[mt][nt][3] * d1v;
            }
        }
#pragma unroll
        for (int q = 0; q < 4; q++) {
            dS[q] += __shfl_xor_sync(0xffffffffu, dS[q], 1);
            dS[q] += __shfl_xor_sync(0xffffffffu, dS[q], 2);
            dD[q] += __shfl_xor_sync(0xffffffffu, dD[q], 1);
            dD[q] += __shfl_xor_sync(0xffffffffu, dD[q], 2);
        }
        if (t == 0) {
#pragma unroll
            for (int q = 0; q < 4; q++) {
                int r = row0 + arow + (q >> 1) * 16 + g + (q & 1) * 8;
                if (r < M) {
                    atomicAdd(&g_as[buf][r * 2 + head], dS[q]);
                    atomicAdd(&g_ad[buf][r * 2 + head], dD[q]);
                }
            }
        }
    }
}

// ------- fused softmax+aggregation (+ optional LN of next block) -------
__global__ void k_agg(const float* __restrict__ bias, const float* __restrict__ resid,
                      float* __restrict__ out, int n, int buf,
                      const float* __restrict__ gn, const float* __restrict__ bn,
                      int do_ln) {
    int node = blockIdx.x * 8 + (threadIdx.x >> 5);
    if (node >= n) return;
    int lane = threadIdx.x & 31;
    int s = g_rowptr[node], t = g_rowptr[node + 1];
    float2 ad = *reinterpret_cast<const float2*>(&g_ad[buf][node * 2]);

    float4 a0 = make_float4(0.f, 0.f, 0.f, 0.f), a1 = a0;
    float s0 = 0.f, s1 = 0.f;
#pragma unroll 2
    for (int e = s; e < t; e++) {
        int c = g_col[e];
        float2 as = *reinterpret_cast<const float2*>(&g_as[buf][c * 2]);
        float e0 = as.x + ad.x; e0 = e0 > 0.f ? e0 : 0.2f * e0;
        float e1 = as.y + ad.y; e1 = e1 > 0.f ? e1 : 0.2f * e1;
        float w0 = __expf(e0), w1 = __expf(e1);
        s0 += w0; s1 += w1;
        uint4 u = *reinterpret_cast<const uint4*>(&g_h[c * 256 + lane * 8]);
        float2 p0 = __bfloat1622float2(*reinterpret_cast<__nv_bfloat162*>(&u.x));
        float2 p1 = __bfloat1622float2(*reinterpret_cast<__nv_bfloat162*>(&u.y));
        float2 p2 = __bfloat1622float2(*reinterpret_cast<__nv_bfloat162*>(&u.z));
        float2 p3 = __bfloat1622float2(*reinterpret_cast<__nv_bfloat162*>(&u.w));
        a0.x += p0.x * w0; a0.y += p0.y * w0; a0.z += p1.x * w0; a0.w += p1.y * w0;
        a1.x += p2.x * w1; a1.y += p2.y * w1; a1.z += p3.x * w1; a1.w += p3.y * w1;
    }
    float i0 = 0.5f / (s0 + 1e-16f);
    float i1 = 0.5f / (s1 + 1e-16f);
    float4 bb = *reinterpret_cast<const float4*>(&bias[lane * 4]);
    float4 rr = *reinterpret_cast<const float4*>(&resid[node * DD + lane * 4]);
    float4 o4;
    o4.x = a0.x * i0 + a1.x * i1 + bb.x + rr.x;
    o4.y = a0.y * i0 + a1.y * i1 + bb.y + rr.y;
    o4.z = a0.z * i0 + a1.z * i1 + bb.z + rr.z;
    o4.w = a0.w * i0 + a1.w * i1 + bb.w + rr.w;
    *reinterpret_cast<float4*>(&out[node * DD + lane * 4]) = o4;

    if (lane == 0) {
        *reinterpret_cast<float2*>(&g_as[buf ^ 1][node * 2]) = make_float2(0.f, 0.f);
        *reinterpret_cast<float2*>(&g_ad[buf ^ 1][node * 2]) = make_float2(0.f, 0.f);
    }

    if (do_ln) {
        float ss = o4.x + o4.y + o4.z + o4.w;
        float qq = o4.x * o4.x + o4.y * o4.y + o4.z * o4.z + o4.w * o4.w;
#pragma unroll
        for (int o = 16; o > 0; o >>= 1) {
            ss += __shfl_xor_sync(0xffffffffu, ss, o);
            qq += __shfl_xor_sync(0xffffffffu, qq, o);
        }
        float mu  = ss * (1.0f / DD);
        float var = qq * (1.0f / DD) - mu * mu;
        float rs  = rsqrtf(var + 1e-5f);
        float4 g4 = *reinterpret_cast<const float4*>(&gn[lane * 4]);
        float4 b4 = *reinterpret_cast<const float4*>(&bn[lane * 4]);
        uint4 u;
        u.x = f2tf32(fmaxf(0.f, (o4.x - mu) * rs * g4.x + b4.x));
        u.y = f2tf32(fmaxf(0.f, (o4.y - mu) * rs * g4.y + b4.y));
        u.z = f2tf32(fmaxf(0.f, (o4.z - mu) * rs * g4.z + b4.z));
        u.w = f2tf32(fmaxf(0.f, (o4.w - mu) * rs * g4.w + b4.w));
        *reinterpret_cast<uint4*>(&g_xn[node * DD + lane * 4]) = u;
    }
}

// ---------------- launch ----------------
extern "C" void kernel_launch(void* const* d_in, const int* in_sizes, int n_in,
                              void* d_out, int out_size) {
    const float* x       = (const float*)d_in[0];
    const int*   ei      = (const int*)d_in[1];
    const float* W       = (const float*)d_in[2];
    const float* att_src = (const float*)d_in[3];
    const float* att_dst = (const float*)d_in[4];
    const float* bias    = (const float*)d_in[5];
    const float* gamma   = (const float*)d_in[6];
    const float* beta    = (const float*)d_in[7];
    float* out = (float*)d_out;

    int Nn  = in_sizes[0] / DD;
    int E   = in_sizes[1] / 2;
    int tot = E + Nn;

    cudaFuncSetAttribute(k_gemm, cudaFuncAttributeMaxDynamicSharedMemorySize, GEMM_SMEM);

    // fork: CSR build on s2, LN + GEMM0 on main stream, join before agg0
    cudaStream_t s2;
    cudaStreamCreateWithFlags(&s2, cudaStreamNonBlocking);
    cudaEvent_t evF, evC;
    cudaEventCreateWithFlags(&evF, cudaEventDisableTiming);
    cudaEventCreateWithFlags(&evC, cudaEventDisableTiming);

    cudaEventRecord(evF, 0);
    cudaStreamWaitEvent(s2, evF, 0);
    k_init<<<(Nn + 255) / 256, 256, 0, s2>>>(Nn);
    k_count<<<(E + 255) / 256, 256, 0, s2>>>(ei, E);
    k_scan1<<<(Nn + 1023) / 1024, 1024, 0, s2>>>(Nn);
    k_scan3<<<(Nn + 255) / 256, 256, 0, s2>>>(Nn, tot);
    k_scatter<<<(tot + 255) / 256, 256, 0, s2>>>(ei, E, Nn);
    cudaEventRecord(evC, s2);

    k_ln<<<(Nn + 7) / 8, 256>>>(x, gamma, beta, Nn);

    for (int b = 0; b < 3; b++) {
        const float* xc = (b == 0) ? x : (const float*)out;
        int buf = b & 1;
        dim3 gg((Nn + 127) / 128, 2);
        k_gemm<<<gg, 256, GEMM_SMEM>>>(W + b * DD * HH * CC,
                                       att_src + b * HH * CC, att_dst + b * HH * CC,
                                       buf, Nn);
        if (b == 0) cudaStreamWaitEvent(0, evC, 0);   // join CSR before first agg
        int do_ln = (b < 2) ? 1 : 0;
        const float* gn = gamma + (b + 1 < 3 ? (b + 1) * DD : 0);
        const float* bn = beta  + (b + 1 < 3 ? (b + 1) * DD : 0);
        k_agg<<<(Nn + 7) / 8, 256>>>(bias + b * CC, xc, out, Nn, buf, gn, bn, do_ln);
    }

    cudaEventDestroy(evF);
    cudaEventDestroy(evC);
    cudaStreamDestroy(s2);
}